// round 5
// baseline (speedup 1.0000x reference)
#include <cuda_runtime.h>
#include <cuda_bf16.h>
#include <cstdint>
#include <math.h>

// Problem shapes (fixed by the dataset)
#define BATCH 4
#define SEQ   2048
#define HID   1024
#define DIM   1024
#define SCALE 0.03125f   // 1/sqrt(1024)

typedef __nv_bfloat16 bf16;
typedef __nv_bfloat162 bf162;

// Scratch (device globals; runtime allocation is forbidden)
__device__ float g_P[(long)BATCH * SEQ * SEQ];
__device__ bf16 g_Xhi[(long)BATCH * SEQ * HID];
__device__ bf16 g_Xlo[(long)BATCH * SEQ * HID];
__device__ bf16 g_Wqh[(long)HID * DIM];
__device__ bf16 g_Wql[(long)HID * DIM];
__device__ bf16 g_Wkh[(long)HID * DIM];
__device__ bf16 g_Wkl[(long)HID * DIM];
__device__ bf16 g_Wvh[(long)HID * DIM];
__device__ bf16 g_Wvl[(long)HID * DIM];
__device__ bf16 g_Qh[(long)BATCH * SEQ * DIM];
__device__ bf16 g_Ql[(long)BATCH * SEQ * DIM];
__device__ bf16 g_Kh[(long)BATCH * SEQ * DIM];
__device__ bf16 g_Kl[(long)BATCH * SEQ * DIM];
__device__ bf16 g_Vh[(long)BATCH * SEQ * DIM];
__device__ bf16 g_Vl[(long)BATCH * SEQ * DIM];
__device__ bf16 g_Ph[(long)BATCH * SEQ * SEQ];
__device__ bf16 g_Pl[(long)BATCH * SEQ * SEQ];

// ---------------------------------------------------------------------------
// PTX helpers (baseline sm_80-level PTX — safe for plain sm_103 target)
// ---------------------------------------------------------------------------
__device__ __forceinline__ uint32_t smem_u32(const void* p) {
    uint32_t a;
    asm("{ .reg .u64 t; cvta.to.shared.u64 t, %1; cvt.u32.u64 %0, t; }"
        : "=r"(a) : "l"(p));
    return a;
}

__device__ __forceinline__ void cpa16(uint32_t dst, const void* src) {
    asm volatile("cp.async.cg.shared.global [%0], [%1], 16;"
                 :: "r"(dst), "l"(src));
}
#define CP_COMMIT() asm volatile("cp.async.commit_group;" ::: "memory")
#define CP_WAIT0()  asm volatile("cp.async.wait_group 0;" ::: "memory")

__device__ __forceinline__ void ldsm_x4(uint32_t* r, uint32_t addr) {
    asm volatile("ldmatrix.sync.aligned.m8n8.x4.shared.b16 {%0,%1,%2,%3}, [%4];"
                 : "=r"(r[0]), "=r"(r[1]), "=r"(r[2]), "=r"(r[3]) : "r"(addr));
}
__device__ __forceinline__ void ldsm_x4_t(uint32_t* r, uint32_t addr) {
    asm volatile("ldmatrix.sync.aligned.m8n8.x4.trans.shared.b16 {%0,%1,%2,%3}, [%4];"
                 : "=r"(r[0]), "=r"(r[1]), "=r"(r[2]), "=r"(r[3]) : "r"(addr));
}

__device__ __forceinline__ void mma_bf16(float* c, const uint32_t* a,
                                         const uint32_t* b) {
    asm volatile(
        "mma.sync.aligned.m16n8k16.row.col.f32.bf16.bf16.f32 "
        "{%0,%1,%2,%3}, {%4,%5,%6,%7}, {%8,%9}, {%0,%1,%2,%3};"
        : "+f"(c[0]), "+f"(c[1]), "+f"(c[2]), "+f"(c[3])
        : "r"(a[0]), "r"(a[1]), "r"(a[2]), "r"(a[3]), "r"(b[0]), "r"(b[1]));
}

// ---------------------------------------------------------------------------
// fp32 -> (hi, lo) bf16 split, elementwise (n multiple of 4)
// ---------------------------------------------------------------------------
__global__ __launch_bounds__(256)
void split_fp32(const float* __restrict__ src, bf16* __restrict__ hi,
                bf16* __restrict__ lo, long n4)
{
    long i = blockIdx.x * 256 + threadIdx.x;
    long stride = (long)gridDim.x * 256;
    for (; i < n4; i += stride) {
        float4 v = *(const float4*)(src + i * 4);
        bf16 hx = __float2bfloat16(v.x), hy = __float2bfloat16(v.y);
        bf16 hz = __float2bfloat16(v.z), hw = __float2bfloat16(v.w);
        bf162 h0 = __halves2bfloat162(hx, hy);
        bf162 h1 = __halves2bfloat162(hz, hw);
        bf162 l0 = __halves2bfloat162(__float2bfloat16(v.x - __bfloat162float(hx)),
                                      __float2bfloat16(v.y - __bfloat162float(hy)));
        bf162 l1 = __halves2bfloat162(__float2bfloat16(v.z - __bfloat162float(hz)),
                                      __float2bfloat16(v.w - __bfloat162float(hw)));
        uint2 hu, lu;
        hu.x = reinterpret_cast<uint32_t&>(h0); hu.y = reinterpret_cast<uint32_t&>(h1);
        lu.x = reinterpret_cast<uint32_t&>(l0); lu.y = reinterpret_cast<uint32_t&>(l1);
        *(uint2*)(hi + i * 4) = hu;
        *(uint2*)(lo + i * 4) = lu;
    }
}

// ---------------------------------------------------------------------------
// HMMA GEMM on pre-split bf16 operands, cp.async double-buffered.
//   C = alpha * (Ahi+Alo) @ op(Bhi+Blo)   [3-term Markidis]
//   A: [M,K] bf16. TRANSB: B is [N,K] (NT); else [K,N] (NN).
//   BM=BN=128, BK=32. 256 threads, 8 warps (4m x 2n), warp tile 32x64.
//   SPLIT_OUT: epilogue writes hi/lo bf16 (for GEMM-consumed outputs);
//   else fp32 to Cf.
// ---------------------------------------------------------------------------
#define ASTR 40    // bf16 row stride A / B(NT): 80B, ldmatrix conflict-free
#define BSTR 136   // bf16 row stride B(NN) [k][n]: 272B, conflict-free

template <bool TRANSB, bool CAUSAL_SKIP, bool KBOUND, bool SPLIT_OUT>
__global__ __launch_bounds__(256)
void gemm_bf(const bf16* __restrict__ Ahi, const bf16* __restrict__ Alo,
             const bf16* __restrict__ Bhi, const bf16* __restrict__ Blo,
             float* __restrict__ Cf, bf16* __restrict__ Chi, bf16* __restrict__ Clo,
             int K, int lda, int ldb, int ldc,
             long sA, long sB, long sC, float alpha)
{
    constexpr int ASZ = 128 * ASTR;                        // elems per A array
    constexpr int BSZ = TRANSB ? 128 * ASTR : 32 * BSTR;   // elems per B array
    constexpr int STG = 2 * ASZ + 2 * BSZ;                 // elems per stage

    extern __shared__ bf16 smem[];

    const int m0 = blockIdx.y * 128;
    const int n0 = blockIdx.x * 128;
    if (CAUSAL_SKIP && n0 > m0 + 127) return;

    Ahi += blockIdx.z * sA; Alo += blockIdx.z * sA;
    Bhi += blockIdx.z * sB; Blo += blockIdx.z * sB;
    if (SPLIT_OUT) { Chi += blockIdx.z * sC; Clo += blockIdx.z * sC; }
    else           { Cf  += blockIdx.z * sC; }

    const int tid  = threadIdx.x;
    const int lane = tid & 31;
    const int wm   = ((tid >> 5) & 3) * 32;
    const int wn   = (tid >> 7) * 64;

    // stage base smem addresses
    uint32_t aHiS[2], aLoS[2], bHiS[2], bLoS[2];
    #pragma unroll
    for (int s = 0; s < 2; ++s) {
        uint32_t base = smem_u32(smem + s * STG);
        aHiS[s] = base;
        aLoS[s] = base + ASZ * 2;
        bHiS[s] = base + 2 * ASZ * 2;
        bLoS[s] = base + (2 * ASZ + BSZ) * 2;
    }

    int kEnd = K;
    if (KBOUND) kEnd = min(K, m0 + 128);

    // cp.async issue for one k-tile into stage s
    auto issue = [&](int kt, int s) {
        #pragma unroll
        for (int i = 0; i < 2; ++i) {
            int q = tid + i * 256;          // chunk id 0..511
            // A tile: r = q>>2 (0..127), c = (q&3)*8
            {
                int r = q >> 2, c = (q & 3) * 8;
                uint32_t doff = (uint32_t)(r * ASTR + c) * 2;
                const bf16* src = Ahi + (long)(m0 + r) * lda + kt + c;
                cpa16(aHiS[s] + doff, src);
                src = Alo + (long)(m0 + r) * lda + kt + c;
                cpa16(aLoS[s] + doff, src);
            }
            if (TRANSB) {
                int r = q >> 2, c = (q & 3) * 8;
                uint32_t doff = (uint32_t)(r * ASTR + c) * 2;
                const bf16* src = Bhi + (long)(n0 + r) * ldb + kt + c;
                cpa16(bHiS[s] + doff, src);
                src = Blo + (long)(n0 + r) * ldb + kt + c;
                cpa16(bLoS[s] + doff, src);
            } else {
                int kk = q >> 4, nn = (q & 15) * 8;
                uint32_t doff = (uint32_t)(kk * BSTR + nn) * 2;
                const bf16* src = Bhi + (long)(kt + kk) * ldb + n0 + nn;
                cpa16(bHiS[s] + doff, src);
                src = Blo + (long)(kt + kk) * ldb + n0 + nn;
                cpa16(bLoS[s] + doff, src);
            }
        }
        CP_COMMIT();
    };

    float acc[2][8][4];
    #pragma unroll
    for (int i = 0; i < 2; ++i)
        #pragma unroll
        for (int j = 0; j < 8; ++j)
            #pragma unroll
            for (int t = 0; t < 4; ++t) acc[i][j][t] = 0.f;

    int s = 0;
    issue(0, 0);

    for (int kt = 0; kt < kEnd; kt += 32) {
        CP_WAIT0();
        __syncthreads();
        if (kt + 32 < kEnd) issue(kt + 32, s ^ 1);

        #pragma unroll
        for (int ks = 0; ks < 2; ++ks) {
            uint32_t aH[2][4], aL[2][4];
            #pragma unroll
            for (int mt = 0; mt < 2; ++mt) {
                uint32_t off =
                    ((uint32_t)(wm + mt * 16 + (lane & 15)) * ASTR +
                     ks * 16 + (lane >> 4) * 8) * 2;
                ldsm_x4(aH[mt], aHiS[s] + off);
                ldsm_x4(aL[mt], aLoS[s] + off);
            }
            #pragma unroll
            for (int np = 0; np < 4; ++np) {
                uint32_t bH[4], bL[4];
                if (TRANSB) {
                    uint32_t nrow = wn + np * 16 + (lane & 7) + (lane >> 4) * 8;
                    uint32_t off = (nrow * ASTR + ks * 16 + ((lane >> 3) & 1) * 8) * 2;
                    ldsm_x4(bH, bHiS[s] + off);
                    ldsm_x4(bL, bLoS[s] + off);
                } else {
                    uint32_t krow = ks * 16 + (lane & 15);
                    uint32_t ncol = wn + np * 16 + (lane >> 4) * 8;
                    uint32_t off = (krow * BSTR + ncol) * 2;
                    ldsm_x4_t(bH, bHiS[s] + off);
                    ldsm_x4_t(bL, bLoS[s] + off);
                }
                #pragma unroll
                for (int h = 0; h < 2; ++h) {
                    #pragma unroll
                    for (int mt = 0; mt < 2; ++mt) {
                        float* c = acc[mt][np * 2 + h];
                        mma_bf16(c, aH[mt], bH + h * 2);
                        mma_bf16(c, aH[mt], bL + h * 2);
                        mma_bf16(c, aL[mt], bH + h * 2);
                    }
                }
            }
        }
        s ^= 1;
    }

    // ---- epilogue ----
    #pragma unroll
    for (int mt = 0; mt < 2; ++mt) {
        #pragma unroll
        for (int nt = 0; nt < 8; ++nt) {
            int row = m0 + wm + mt * 16 + (lane >> 2);
            int col = n0 + wn + nt * 8 + (lane & 3) * 2;
            float c0 = alpha * acc[mt][nt][0];
            float c1 = alpha * acc[mt][nt][1];
            float c2 = alpha * acc[mt][nt][2];
            float c3 = alpha * acc[mt][nt][3];
            if (SPLIT_OUT) {
                bf16 h0 = __float2bfloat16(c0), h1 = __float2bfloat16(c1);
                bf16 h2 = __float2bfloat16(c2), h3 = __float2bfloat16(c3);
                bf162 hv0 = __halves2bfloat162(h0, h1);
                bf162 hv1 = __halves2bfloat162(h2, h3);
                bf162 lv0 = __halves2bfloat162(
                    __float2bfloat16(c0 - __bfloat162float(h0)),
                    __float2bfloat16(c1 - __bfloat162float(h1)));
                bf162 lv1 = __halves2bfloat162(
                    __float2bfloat16(c2 - __bfloat162float(h2)),
                    __float2bfloat16(c3 - __bfloat162float(h3)));
                *(bf162*)(Chi + (long)row * ldc + col) = hv0;
                *(bf162*)(Clo + (long)row * ldc + col) = lv0;
                *(bf162*)(Chi + (long)(row + 8) * ldc + col) = hv1;
                *(bf162*)(Clo + (long)(row + 8) * ldc + col) = lv1;
            } else {
                *(float2*)(Cf + (long)row * ldc + col) = make_float2(c0, c1);
                *(float2*)(Cf + (long)(row + 8) * ldc + col) = make_float2(c2, c3);
            }
        }
    }
}

// ---------------------------------------------------------------------------
// Causal softmax: reads fp32 scores row, writes hi/lo bf16 probabilities
// (zeros beyond the diagonal) for the PV GEMM.
// ---------------------------------------------------------------------------
__global__ __launch_bounds__(256)
void softmax_causal(const float* __restrict__ P, bf16* __restrict__ Ph,
                    bf16* __restrict__ Pl)
{
    const int S = SEQ;
    const int i = blockIdx.x;
    const int b = blockIdx.y;
    const float* row = P + ((long)b * S + (long)i) * S;
    bf16* hrow = Ph + ((long)b * S + (long)i) * S;
    bf16* lrow = Pl + ((long)b * S + (long)i) * S;

    __shared__ float buf[SEQ];
    __shared__ float red[256];
    const int tid = threadIdx.x;
    const int L = i + 1;

    float m = -3.0e38f;
    for (int j = tid; j < L; j += 256) {
        float v = row[j];
        buf[j] = v;
        m = fmaxf(m, v);
    }
    red[tid] = m;
    __syncthreads();
    #pragma unroll
    for (int sd = 128; sd > 0; sd >>= 1) {
        if (tid < sd) red[tid] = fmaxf(red[tid], red[tid + sd]);
        __syncthreads();
    }
    m = red[0];
    __syncthreads();

    float sum = 0.f;
    for (int j = tid; j < L; j += 256) {
        float e = expf(buf[j] - m);
        buf[j] = e;
        sum += e;
    }
    red[tid] = sum;
    __syncthreads();
    #pragma unroll
    for (int sd = 128; sd > 0; sd >>= 1) {
        if (tid < sd) red[tid] += red[tid + sd];
        __syncthreads();
    }
    const float inv = 1.0f / red[0];

    for (int j = tid; j < S; j += 256) {
        float v = (j < L) ? buf[j] * inv : 0.f;
        bf16 h = __float2bfloat16(v);
        hrow[j] = h;
        lrow[j] = __float2bfloat16(v - __bfloat162float(h));
    }
}

// ---------------------------------------------------------------------------
extern "C" void kernel_launch(void* const* d_in, const int* in_sizes, int n_in,
                              void* d_out, int out_size)
{
    (void)in_sizes; (void)n_in; (void)out_size;
    const float* X  = (const float*)d_in[0];
    const float* Wq = (const float*)d_in[1];
    const float* Wk = (const float*)d_in[2];
    const float* Wv = (const float*)d_in[3];
    float* out = (float*)d_out;

    #define SYM(v, s) void* v; cudaGetSymbolAddress(&v, s)
    SYM(pP, g_P);
    SYM(pXh, g_Xhi); SYM(pXl, g_Xlo);
    SYM(pWqh, g_Wqh); SYM(pWql, g_Wql);
    SYM(pWkh, g_Wkh); SYM(pWkl, g_Wkl);
    SYM(pWvh, g_Wvh); SYM(pWvl, g_Wvl);
    SYM(pQh, g_Qh); SYM(pQl, g_Ql);
    SYM(pKh, g_Kh); SYM(pKl, g_Kl);
    SYM(pVh, g_Vh); SYM(pVl, g_Vl);
    SYM(pPh, g_Ph); SYM(pPl, g_Pl);
    #undef SYM

    const long perQ = (long)SEQ * DIM;
    const long perP = (long)SEQ * SEQ;

    // smem sizes per variant
    const int NT_SMEM = 2 * (4 * 128 * ASTR) * 2;                  // 81920 B
    const int NN_SMEM = 2 * (2 * 128 * ASTR + 2 * 32 * BSTR) * 2;  // 75776 B

    cudaFuncSetAttribute(gemm_bf<false, false, false, true>,
                         cudaFuncAttributeMaxDynamicSharedMemorySize, NN_SMEM);
    cudaFuncSetAttribute(gemm_bf<true, true, false, false>,
                         cudaFuncAttributeMaxDynamicSharedMemorySize, NT_SMEM);
    cudaFuncSetAttribute(gemm_bf<false, false, true, false>,
                         cudaFuncAttributeMaxDynamicSharedMemorySize, NN_SMEM);

    // 0) split X and weights to bf16 hi/lo
    {
        long nX = (long)BATCH * SEQ * HID / 4;
        split_fp32<<<2048, 256>>>(X, (bf16*)pXh, (bf16*)pXl, nX);
        long nW = (long)HID * DIM / 4;
        split_fp32<<<512, 256>>>(Wq, (bf16*)pWqh, (bf16*)pWql, nW);
        split_fp32<<<512, 256>>>(Wk, (bf16*)pWkh, (bf16*)pWkl, nW);
        split_fp32<<<512, 256>>>(Wv, (bf16*)pWvh, (bf16*)pWvl, nW);
    }

    // 1) QKV projections: [B*S, H] @ [H, D] -> hi/lo bf16 outputs
    {
        dim3 grid(DIM / 128, (BATCH * SEQ) / 128, 1);
        gemm_bf<false, false, false, true><<<grid, 256, NN_SMEM>>>(
            (bf16*)pXh, (bf16*)pXl, (bf16*)pWqh, (bf16*)pWql,
            nullptr, (bf16*)pQh, (bf16*)pQl,
            HID, HID, DIM, DIM, 0, 0, 0, 1.0f);
        gemm_bf<false, false, false, true><<<grid, 256, NN_SMEM>>>(
            (bf16*)pXh, (bf16*)pXl, (bf16*)pWkh, (bf16*)pWkl,
            nullptr, (bf16*)pKh, (bf16*)pKl,
            HID, HID, DIM, DIM, 0, 0, 0, 1.0f);
        gemm_bf<false, false, false, true><<<grid, 256, NN_SMEM>>>(
            (bf16*)pXh, (bf16*)pXl, (bf16*)pWvh, (bf16*)pWvl,
            nullptr, (bf16*)pVh, (bf16*)pVl,
            HID, HID, DIM, DIM, 0, 0, 0, 1.0f);
    }

    // 2) scores = (Q @ K^T) * (1/sqrt(D)) -> fp32 P, lower-tri blocks only
    {
        dim3 grid(SEQ / 128, SEQ / 128, BATCH);
        gemm_bf<true, true, false, false><<<grid, 256, NT_SMEM>>>(
            (bf16*)pQh, (bf16*)pQl, (bf16*)pKh, (bf16*)pKl,
            (float*)pP, nullptr, nullptr,
            DIM, DIM, DIM, SEQ, perQ, perQ, perP, SCALE);
    }

    // 3) causal softmax -> hi/lo bf16 probabilities (zeros above diagonal)
    {
        dim3 grid(SEQ, BATCH);
        softmax_causal<<<grid, 256>>>((float*)pP, (bf16*)pPh, (bf16*)pPl);
    }

    // 4) out = P @ V (fp32 out), K bounded per M-tile by causality
    {
        dim3 grid(DIM / 128, SEQ / 128, BATCH);
        gemm_bf<false, false, true, false><<<grid, 256, NN_SMEM>>>(
            (bf16*)pPh, (bf16*)pPl, (bf16*)pVh, (bf16*)pVl,
            out, nullptr, nullptr,
            SEQ, SEQ, DIM, DIM, perP, perQ, perQ, 1.0f);
    }
}

// round 6
// speedup vs baseline: 1.0035x; 1.0035x over previous
#include <cuda_runtime.h>
#include <cuda_bf16.h>
#include <cstdint>
#include <math.h>

// Problem shapes (fixed by the dataset)
#define BATCH 4
#define SEQ   2048
#define HID   1024
#define DIM   1024
#define SCALE 0.03125f   // 1/sqrt(1024)

typedef __nv_bfloat16 bf16;
typedef __nv_bfloat162 bf162;

// Scratch (device globals; runtime allocation is forbidden)
__device__ float g_P[(long)BATCH * SEQ * SEQ];
__device__ bf16 g_Xhi[(long)BATCH * SEQ * HID];
__device__ bf16 g_Xlo[(long)BATCH * SEQ * HID];
__device__ bf16 g_Wqh[(long)HID * DIM];
__device__ bf16 g_Wql[(long)HID * DIM];
__device__ bf16 g_Wkh[(long)HID * DIM];
__device__ bf16 g_Wkl[(long)HID * DIM];
__device__ bf16 g_Wvh[(long)HID * DIM];
__device__ bf16 g_Wvl[(long)HID * DIM];
__device__ bf16 g_Qh[(long)BATCH * SEQ * DIM];
__device__ bf16 g_Ql[(long)BATCH * SEQ * DIM];
__device__ bf16 g_Kh[(long)BATCH * SEQ * DIM];
__device__ bf16 g_Kl[(long)BATCH * SEQ * DIM];
__device__ bf16 g_Vh[(long)BATCH * SEQ * DIM];
__device__ bf16 g_Vl[(long)BATCH * SEQ * DIM];
__device__ bf16 g_Ph[(long)BATCH * SEQ * SEQ];
__device__ bf16 g_Pl[(long)BATCH * SEQ * SEQ];

// ---------------------------------------------------------------------------
// PTX helpers (baseline sm_80-level PTX — safe for plain sm_103 target)
// ---------------------------------------------------------------------------
__device__ __forceinline__ uint32_t smem_u32(const void* p) {
    uint32_t a;
    asm("{ .reg .u64 t; cvta.to.shared.u64 t, %1; cvt.u32.u64 %0, t; }"
        : "=r"(a) : "l"(p));
    return a;
}

__device__ __forceinline__ void cpa16(uint32_t dst, const void* src) {
    asm volatile("cp.async.cg.shared.global [%0], [%1], 16;"
                 :: "r"(dst), "l"(src));
}
#define CP_COMMIT() asm volatile("cp.async.commit_group;" ::: "memory")
#define CP_WAIT1()  asm volatile("cp.async.wait_group 1;" ::: "memory")

__device__ __forceinline__ void ldsm_x4(uint32_t* r, uint32_t addr) {
    asm volatile("ldmatrix.sync.aligned.m8n8.x4.shared.b16 {%0,%1,%2,%3}, [%4];"
                 : "=r"(r[0]), "=r"(r[1]), "=r"(r[2]), "=r"(r[3]) : "r"(addr));
}
__device__ __forceinline__ void ldsm_x4_t(uint32_t* r, uint32_t addr) {
    asm volatile("ldmatrix.sync.aligned.m8n8.x4.trans.shared.b16 {%0,%1,%2,%3}, [%4];"
                 : "=r"(r[0]), "=r"(r[1]), "=r"(r[2]), "=r"(r[3]) : "r"(addr));
}

__device__ __forceinline__ void mma_bf16(float* c, const uint32_t* a,
                                         const uint32_t* b) {
    asm volatile(
        "mma.sync.aligned.m16n8k16.row.col.f32.bf16.bf16.f32 "
        "{%0,%1,%2,%3}, {%4,%5,%6,%7}, {%8,%9}, {%0,%1,%2,%3};"
        : "+f"(c[0]), "+f"(c[1]), "+f"(c[2]), "+f"(c[3])
        : "r"(a[0]), "r"(a[1]), "r"(a[2]), "r"(a[3]), "r"(b[0]), "r"(b[1]));
}

// ---------------------------------------------------------------------------
// fp32 -> (hi, lo) bf16 split, elementwise (n multiple of 4)
// ---------------------------------------------------------------------------
__global__ __launch_bounds__(256)
void split_fp32(const float* __restrict__ src, bf16* __restrict__ hi,
                bf16* __restrict__ lo, long n4)
{
    long i = blockIdx.x * 256 + threadIdx.x;
    long stride = (long)gridDim.x * 256;
    for (; i < n4; i += stride) {
        float4 v = *(const float4*)(src + i * 4);
        bf16 hx = __float2bfloat16(v.x), hy = __float2bfloat16(v.y);
        bf16 hz = __float2bfloat16(v.z), hw = __float2bfloat16(v.w);
        bf162 h0 = __halves2bfloat162(hx, hy);
        bf162 h1 = __halves2bfloat162(hz, hw);
        bf162 l0 = __halves2bfloat162(__float2bfloat16(v.x - __bfloat162float(hx)),
                                      __float2bfloat16(v.y - __bfloat162float(hy)));
        bf162 l1 = __halves2bfloat162(__float2bfloat16(v.z - __bfloat162float(hz)),
                                      __float2bfloat16(v.w - __bfloat162float(hw)));
        uint2 hu, lu;
        hu.x = reinterpret_cast<uint32_t&>(h0); hu.y = reinterpret_cast<uint32_t&>(h1);
        lu.x = reinterpret_cast<uint32_t&>(l0); lu.y = reinterpret_cast<uint32_t&>(l1);
        *(uint2*)(hi + i * 4) = hu;
        *(uint2*)(lo + i * 4) = lu;
    }
}

// ---------------------------------------------------------------------------
// HMMA GEMM on pre-split bf16, 3-stage cp.async pipeline, 512 threads.
//   C = alpha * (Ahi+Alo) @ op(Bhi+Blo)   [3-term Markidis]
//   BM=BN=128, BK=32. 16 warps (4m x 4n), warp tile 32x32.
// ---------------------------------------------------------------------------
#define ASTR 40    // bf16 row stride A / B(NT): 80B, ldmatrix conflict-free
#define BSTR 136   // bf16 row stride B(NN) [k][n]: 272B, conflict-free
#define NSTG 3

template <bool TRANSB, bool CAUSAL_SKIP, bool KBOUND, bool SPLIT_OUT>
__global__ __launch_bounds__(512)
void gemm_bf(const bf16* __restrict__ Ahi, const bf16* __restrict__ Alo,
             const bf16* __restrict__ Bhi, const bf16* __restrict__ Blo,
             float* __restrict__ Cf, bf16* __restrict__ Chi, bf16* __restrict__ Clo,
             int K, int lda, int ldb, int ldc,
             long sA, long sB, long sC, float alpha)
{
    constexpr int ASZ = 128 * ASTR;                        // elems per A array
    constexpr int BSZ = TRANSB ? 128 * ASTR : 32 * BSTR;   // elems per B array
    constexpr int STG = 2 * ASZ + 2 * BSZ;                 // elems per stage

    extern __shared__ bf16 smem[];

    const int m0 = blockIdx.y * 128;
    const int n0 = blockIdx.x * 128;
    if (CAUSAL_SKIP && n0 > m0 + 127) return;

    Ahi += blockIdx.z * sA; Alo += blockIdx.z * sA;
    Bhi += blockIdx.z * sB; Blo += blockIdx.z * sB;
    if (SPLIT_OUT) { Chi += blockIdx.z * sC; Clo += blockIdx.z * sC; }
    else           { Cf  += blockIdx.z * sC; }

    const int tid  = threadIdx.x;
    const int lane = tid & 31;
    const int wid  = tid >> 5;
    const int wm   = (wid & 3) * 32;    // warp m-offset
    const int wn   = (wid >> 2) * 32;   // warp n-offset

    uint32_t aHiS[NSTG], aLoS[NSTG], bHiS[NSTG], bLoS[NSTG];
    #pragma unroll
    for (int s = 0; s < NSTG; ++s) {
        uint32_t base = smem_u32(smem + s * STG);
        aHiS[s] = base;
        aLoS[s] = base + ASZ * 2;
        bHiS[s] = base + 2 * ASZ * 2;
        bLoS[s] = base + (2 * ASZ + BSZ) * 2;
    }

    int kEnd = K;
    if (KBOUND) kEnd = min(K, m0 + 128);

    // cp.async issue for one k-tile into stage s. Always commits (uniform
    // group counting; empty groups complete immediately).
    auto issue = [&](int kt, int s) {
        if (kt < kEnd) {
            // A: 512 chunks of 8 bf16, one per thread per array
            int r = tid >> 2, c = (tid & 3) * 8;
            uint32_t doff = (uint32_t)(r * ASTR + c) * 2;
            cpa16(aHiS[s] + doff, Ahi + (long)(m0 + r) * lda + kt + c);
            cpa16(aLoS[s] + doff, Alo + (long)(m0 + r) * lda + kt + c);
            if (TRANSB) {
                cpa16(bHiS[s] + doff, Bhi + (long)(n0 + r) * ldb + kt + c);
                cpa16(bLoS[s] + doff, Blo + (long)(n0 + r) * ldb + kt + c);
            } else {
                int kk = tid >> 4, nn = (tid & 15) * 8;
                uint32_t boff = (uint32_t)(kk * BSTR + nn) * 2;
                cpa16(bHiS[s] + boff, Bhi + (long)(kt + kk) * ldb + n0 + nn);
                cpa16(bLoS[s] + boff, Blo + (long)(kt + kk) * ldb + n0 + nn);
            }
        }
        CP_COMMIT();
    };

    float acc[2][4][4];   // [mt][np*2+h][quad]
    #pragma unroll
    for (int i = 0; i < 2; ++i)
        #pragma unroll
        for (int j = 0; j < 4; ++j)
            #pragma unroll
            for (int t = 0; t < 4; ++t) acc[i][j][t] = 0.f;

    issue(0, 0);
    issue(32, 1);

    int s = 0;
    for (int kt = 0; kt < kEnd; kt += 32) {
        CP_WAIT1();
        __syncthreads();
        issue(kt + 64, (s + 2) % NSTG);   // overwrites stage computed last iter

        #pragma unroll
        for (int ks = 0; ks < 2; ++ks) {
            uint32_t aH[2][4], aL[2][4];
            #pragma unroll
            for (int mt = 0; mt < 2; ++mt) {
                uint32_t off =
                    ((uint32_t)(wm + mt * 16 + (lane & 15)) * ASTR +
                     ks * 16 + (lane >> 4) * 8) * 2;
                ldsm_x4(aH[mt], aHiS[s] + off);
                ldsm_x4(aL[mt], aLoS[s] + off);
            }
            #pragma unroll
            for (int np = 0; np < 2; ++np) {
                uint32_t bH[4], bL[4];
                if (TRANSB) {
                    uint32_t nrow = wn + np * 16 + (lane & 7) + (lane >> 4) * 8;
                    uint32_t off = (nrow * ASTR + ks * 16 + ((lane >> 3) & 1) * 8) * 2;
                    ldsm_x4(bH, bHiS[s] + off);
                    ldsm_x4(bL, bLoS[s] + off);
                } else {
                    uint32_t krow = ks * 16 + (lane & 15);
                    uint32_t ncol = wn + np * 16 + (lane >> 4) * 8;
                    uint32_t off = (krow * BSTR + ncol) * 2;
                    ldsm_x4_t(bH, bHiS[s] + off);
                    ldsm_x4_t(bL, bLoS[s] + off);
                }
                #pragma unroll
                for (int h = 0; h < 2; ++h) {
                    #pragma unroll
                    for (int mt = 0; mt < 2; ++mt) {
                        float* c = acc[mt][np * 2 + h];
                        mma_bf16(c, aH[mt], bH + h * 2);
                        mma_bf16(c, aH[mt], bL + h * 2);
                        mma_bf16(c, aL[mt], bH + h * 2);
                    }
                }
            }
        }
        s = (s + 1) % NSTG;
    }

    // ---- epilogue ----
    #pragma unroll
    for (int mt = 0; mt < 2; ++mt) {
        #pragma unroll
        for (int nt = 0; nt < 4; ++nt) {
            int row = m0 + wm + mt * 16 + (lane >> 2);
            int col = n0 + wn + nt * 8 + (lane & 3) * 2;
            float c0 = alpha * acc[mt][nt][0];
            float c1 = alpha * acc[mt][nt][1];
            float c2 = alpha * acc[mt][nt][2];
            float c3 = alpha * acc[mt][nt][3];
            if (SPLIT_OUT) {
                bf16 h0 = __float2bfloat16(c0), h1 = __float2bfloat16(c1);
                bf16 h2 = __float2bfloat16(c2), h3 = __float2bfloat16(c3);
                bf162 hv0 = __halves2bfloat162(h0, h1);
                bf162 hv1 = __halves2bfloat162(h2, h3);
                bf162 lv0 = __halves2bfloat162(
                    __float2bfloat16(c0 - __bfloat162float(h0)),
                    __float2bfloat16(c1 - __bfloat162float(h1)));
                bf162 lv1 = __halves2bfloat162(
                    __float2bfloat16(c2 - __bfloat162float(h2)),
                    __float2bfloat16(c3 - __bfloat162float(h3)));
                *(bf162*)(Chi + (long)row * ldc + col) = hv0;
                *(bf162*)(Clo + (long)row * ldc + col) = lv0;
                *(bf162*)(Chi + (long)(row + 8) * ldc + col) = hv1;
                *(bf162*)(Clo + (long)(row + 8) * ldc + col) = lv1;
            } else {
                *(float2*)(Cf + (long)row * ldc + col) = make_float2(c0, c1);
                *(float2*)(Cf + (long)(row + 8) * ldc + col) = make_float2(c2, c3);
            }
        }
    }
}

// ---------------------------------------------------------------------------
// Causal softmax: reads fp32 scores row, writes hi/lo bf16 probabilities
// (zeros beyond the diagonal) for the PV GEMM.
// ---------------------------------------------------------------------------
__global__ __launch_bounds__(256)
void softmax_causal(const float* __restrict__ P, bf16* __restrict__ Ph,
                    bf16* __restrict__ Pl)
{
    const int S = SEQ;
    const int i = blockIdx.x;
    const int b = blockIdx.y;
    const float* row = P + ((long)b * S + (long)i) * S;
    bf16* hrow = Ph + ((long)b * S + (long)i) * S;
    bf16* lrow = Pl + ((long)b * S + (long)i) * S;

    __shared__ float buf[SEQ];
    __shared__ float red[256];
    const int tid = threadIdx.x;
    const int L = i + 1;

    float m = -3.0e38f;
    for (int j = tid; j < L; j += 256) {
        float v = row[j];
        buf[j] = v;
        m = fmaxf(m, v);
    }
    red[tid] = m;
    __syncthreads();
    #pragma unroll
    for (int sd = 128; sd > 0; sd >>= 1) {
        if (tid < sd) red[tid] = fmaxf(red[tid], red[tid + sd]);
        __syncthreads();
    }
    m = red[0];
    __syncthreads();

    float sum = 0.f;
    for (int j = tid; j < L; j += 256) {
        float e = expf(buf[j] - m);
        buf[j] = e;
        sum += e;
    }
    red[tid] = sum;
    __syncthreads();
    #pragma unroll
    for (int sd = 128; sd > 0; sd >>= 1) {
        if (tid < sd) red[tid] += red[tid + sd];
        __syncthreads();
    }
    const float inv = 1.0f / red[0];

    for (int j = tid; j < S; j += 256) {
        float v = (j < L) ? buf[j] * inv : 0.f;
        bf16 h = __float2bfloat16(v);
        hrow[j] = h;
        lrow[j] = __float2bfloat16(v - __bfloat162float(h));
    }
}

// ---------------------------------------------------------------------------
extern "C" void kernel_launch(void* const* d_in, const int* in_sizes, int n_in,
                              void* d_out, int out_size)
{
    (void)in_sizes; (void)n_in; (void)out_size;
    const float* X  = (const float*)d_in[0];
    const float* Wq = (const float*)d_in[1];
    const float* Wk = (const float*)d_in[2];
    const float* Wv = (const float*)d_in[3];
    float* out = (float*)d_out;

    #define SYM(v, s) void* v; cudaGetSymbolAddress(&v, s)
    SYM(pP, g_P);
    SYM(pXh, g_Xhi); SYM(pXl, g_Xlo);
    SYM(pWqh, g_Wqh); SYM(pWql, g_Wql);
    SYM(pWkh, g_Wkh); SYM(pWkl, g_Wkl);
    SYM(pWvh, g_Wvh); SYM(pWvl, g_Wvl);
    SYM(pQh, g_Qh); SYM(pQl, g_Ql);
    SYM(pKh, g_Kh); SYM(pKl, g_Kl);
    SYM(pVh, g_Vh); SYM(pVl, g_Vl);
    SYM(pPh, g_Ph); SYM(pPl, g_Pl);
    #undef SYM

    const long perQ = (long)SEQ * DIM;
    const long perP = (long)SEQ * SEQ;

    // smem sizes per variant (3 stages)
    const int NT_SMEM = NSTG * (4 * 128 * ASTR) * 2;                   // 122880 B
    const int NN_SMEM = NSTG * (2 * 128 * ASTR + 2 * 32 * BSTR) * 2;   // 113664 B

    cudaFuncSetAttribute(gemm_bf<false, false, false, true>,
                         cudaFuncAttributeMaxDynamicSharedMemorySize, NN_SMEM);
    cudaFuncSetAttribute(gemm_bf<true, true, false, false>,
                         cudaFuncAttributeMaxDynamicSharedMemorySize, NT_SMEM);
    cudaFuncSetAttribute(gemm_bf<false, false, true, false>,
                         cudaFuncAttributeMaxDynamicSharedMemorySize, NN_SMEM);

    // 0) split X and weights to bf16 hi/lo
    {
        long nX = (long)BATCH * SEQ * HID / 4;
        split_fp32<<<2048, 256>>>(X, (bf16*)pXh, (bf16*)pXl, nX);
        long nW = (long)HID * DIM / 4;
        split_fp32<<<512, 256>>>(Wq, (bf16*)pWqh, (bf16*)pWql, nW);
        split_fp32<<<512, 256>>>(Wk, (bf16*)pWkh, (bf16*)pWkl, nW);
        split_fp32<<<512, 256>>>(Wv, (bf16*)pWvh, (bf16*)pWvl, nW);
    }

    // 1) QKV projections: [B*S, H] @ [H, D] -> hi/lo bf16 outputs
    {
        dim3 grid(DIM / 128, (BATCH * SEQ) / 128, 1);
        gemm_bf<false, false, false, true><<<grid, 512, NN_SMEM>>>(
            (bf16*)pXh, (bf16*)pXl, (bf16*)pWqh, (bf16*)pWql,
            nullptr, (bf16*)pQh, (bf16*)pQl,
            HID, HID, DIM, DIM, 0, 0, 0, 1.0f);
        gemm_bf<false, false, false, true><<<grid, 512, NN_SMEM>>>(
            (bf16*)pXh, (bf16*)pXl, (bf16*)pWkh, (bf16*)pWkl,
            nullptr, (bf16*)pKh, (bf16*)pKl,
            HID, HID, DIM, DIM, 0, 0, 0, 1.0f);
        gemm_bf<false, false, false, true><<<grid, 512, NN_SMEM>>>(
            (bf16*)pXh, (bf16*)pXl, (bf16*)pWvh, (bf16*)pWvl,
            nullptr, (bf16*)pVh, (bf16*)pVl,
            HID, HID, DIM, DIM, 0, 0, 0, 1.0f);
    }

    // 2) scores = (Q @ K^T) * (1/sqrt(D)) -> fp32 P, lower-tri blocks only
    {
        dim3 grid(SEQ / 128, SEQ / 128, BATCH);
        gemm_bf<true, true, false, false><<<grid, 512, NT_SMEM>>>(
            (bf16*)pQh, (bf16*)pQl, (bf16*)pKh, (bf16*)pKl,
            (float*)pP, nullptr, nullptr,
            DIM, DIM, DIM, SEQ, perQ, perQ, perP, SCALE);
    }

    // 3) causal softmax -> hi/lo bf16 probabilities (zeros above diagonal)
    {
        dim3 grid(SEQ, BATCH);
        softmax_causal<<<grid, 256>>>((float*)pP, (bf16*)pPh, (bf16*)pPl);
    }

    // 4) out = P @ V (fp32 out), K bounded per M-tile by causality
    {
        dim3 grid(DIM / 128, SEQ / 128, BATCH);
        gemm_bf<false, false, true, false><<<grid, 512, NN_SMEM>>>(
            (bf16*)pPh, (bf16*)pPl, (bf16*)pVh, (bf16*)pVl,
            out, nullptr, nullptr,
            SEQ, SEQ, DIM, DIM, perP, perQ, perQ, 1.0f);
    }
}

// round 7
// speedup vs baseline: 1.0211x; 1.0175x over previous
#include <cuda_runtime.h>
#include <cuda_bf16.h>
#include <cstdint>
#include <math.h>

// Problem shapes (fixed by the dataset)
#define BATCH 4
#define SEQ   2048
#define HID   1024
#define DIM   1024
#define SCALE 0.03125f   // 1/sqrt(1024)

typedef __nv_bfloat16 bf16;
typedef __nv_bfloat162 bf162;

// Scratch (device globals; runtime allocation is forbidden)
__device__ float g_P[(long)BATCH * SEQ * SEQ];
__device__ bf16 g_Xhi[(long)BATCH * SEQ * HID];
__device__ bf16 g_Xlo[(long)BATCH * SEQ * HID];
__device__ bf16 g_Wqh[(long)HID * DIM];
__device__ bf16 g_Wql[(long)HID * DIM];
__device__ bf16 g_Wkh[(long)HID * DIM];
__device__ bf16 g_Wkl[(long)HID * DIM];
__device__ bf16 g_Wvh[(long)HID * DIM];
__device__ bf16 g_Wvl[(long)HID * DIM];
__device__ bf16 g_Qh[(long)BATCH * SEQ * DIM];
__device__ bf16 g_Ql[(long)BATCH * SEQ * DIM];
__device__ bf16 g_Kh[(long)BATCH * SEQ * DIM];
__device__ bf16 g_Kl[(long)BATCH * SEQ * DIM];
__device__ bf16 g_Vh[(long)BATCH * SEQ * DIM];
__device__ bf16 g_Vl[(long)BATCH * SEQ * DIM];
__device__ bf16 g_Ph[(long)BATCH * SEQ * SEQ];
__device__ bf16 g_Pl[(long)BATCH * SEQ * SEQ];

// ---------------------------------------------------------------------------
// PTX helpers (baseline sm_80-level PTX — safe for plain sm_103 target)
// ---------------------------------------------------------------------------
__device__ __forceinline__ uint32_t smem_u32(const void* p) {
    uint32_t a;
    asm("{ .reg .u64 t; cvta.to.shared.u64 t, %1; cvt.u32.u64 %0, t; }"
        : "=r"(a) : "l"(p));
    return a;
}

__device__ __forceinline__ void cpa16(uint32_t dst, const void* src) {
    asm volatile("cp.async.cg.shared.global [%0], [%1], 16;"
                 :: "r"(dst), "l"(src));
}
#define CP_COMMIT() asm volatile("cp.async.commit_group;" ::: "memory")
#define CP_WAIT1()  asm volatile("cp.async.wait_group 1;" ::: "memory")

__device__ __forceinline__ void ldsm_x4(uint32_t* r, uint32_t addr) {
    asm volatile("ldmatrix.sync.aligned.m8n8.x4.shared.b16 {%0,%1,%2,%3}, [%4];"
                 : "=r"(r[0]), "=r"(r[1]), "=r"(r[2]), "=r"(r[3]) : "r"(addr));
}
__device__ __forceinline__ void ldsm_x4_t(uint32_t* r, uint32_t addr) {
    asm volatile("ldmatrix.sync.aligned.m8n8.x4.trans.shared.b16 {%0,%1,%2,%3}, [%4];"
                 : "=r"(r[0]), "=r"(r[1]), "=r"(r[2]), "=r"(r[3]) : "r"(addr));
}

__device__ __forceinline__ void mma_bf16(float* c, const uint32_t* a,
                                         const uint32_t* b) {
    asm volatile(
        "mma.sync.aligned.m16n8k16.row.col.f32.bf16.bf16.f32 "
        "{%0,%1,%2,%3}, {%4,%5,%6,%7}, {%8,%9}, {%0,%1,%2,%3};"
        : "+f"(c[0]), "+f"(c[1]), "+f"(c[2]), "+f"(c[3])
        : "r"(a[0]), "r"(a[1]), "r"(a[2]), "r"(a[3]), "r"(b[0]), "r"(b[1]));
}

// ---------------------------------------------------------------------------
// fp32 -> (hi, lo) bf16 split, elementwise (n multiple of 4)
// ---------------------------------------------------------------------------
__global__ __launch_bounds__(256)
void split_fp32(const float* __restrict__ src, bf16* __restrict__ hi,
                bf16* __restrict__ lo, long n4)
{
    long i = blockIdx.x * 256 + threadIdx.x;
    long stride = (long)gridDim.x * 256;
    for (; i < n4; i += stride) {
        float4 v = *(const float4*)(src + i * 4);
        bf16 hx = __float2bfloat16(v.x), hy = __float2bfloat16(v.y);
        bf16 hz = __float2bfloat16(v.z), hw = __float2bfloat16(v.w);
        bf162 h0 = __halves2bfloat162(hx, hy);
        bf162 h1 = __halves2bfloat162(hz, hw);
        bf162 l0 = __halves2bfloat162(__float2bfloat16(v.x - __bfloat162float(hx)),
                                      __float2bfloat16(v.y - __bfloat162float(hy)));
        bf162 l1 = __halves2bfloat162(__float2bfloat16(v.z - __bfloat162float(hz)),
                                      __float2bfloat16(v.w - __bfloat162float(hw)));
        uint2 hu, lu;
        hu.x = reinterpret_cast<uint32_t&>(h0); hu.y = reinterpret_cast<uint32_t&>(h1);
        lu.x = reinterpret_cast<uint32_t&>(l0); lu.y = reinterpret_cast<uint32_t&>(l1);
        *(uint2*)(hi + i * 4) = hu;
        *(uint2*)(lo + i * 4) = lu;
    }
}

// ---------------------------------------------------------------------------
// Shared GEMM config: BM=BN=128, BK=32, 256 threads, 8 warps (4m x 2n),
// warp tile 32x64. 3-stage cp.async pipeline. 3-term Markidis bf16 split.
// ---------------------------------------------------------------------------
#define ASTR 40    // bf16 row stride A / B(NT): 80B, ldmatrix conflict-free
#define BSTR 136   // bf16 row stride B(NN) [k][n]: 272B, conflict-free
#define NSTG 3

// Inner MMA over one staged k-tile (proven R4 loop). A in [m][k] stride ASTR;
// B in [n][k] stride ASTR (NT) or [k][n] stride BSTR (NN).
template <bool TRANSB>
__device__ __forceinline__ void mma_tile(
    float acc[2][8][4], uint32_t aHi, uint32_t aLo, uint32_t bHi, uint32_t bLo,
    int wm, int wn, int lane)
{
    #pragma unroll
    for (int ks = 0; ks < 2; ++ks) {
        uint32_t aH[2][4], aL[2][4];
        #pragma unroll
        for (int mt = 0; mt < 2; ++mt) {
            uint32_t off =
                ((uint32_t)(wm + mt * 16 + (lane & 15)) * ASTR +
                 ks * 16 + (lane >> 4) * 8) * 2;
            ldsm_x4(aH[mt], aHi + off);
            ldsm_x4(aL[mt], aLo + off);
        }
        #pragma unroll
        for (int np = 0; np < 4; ++np) {
            uint32_t bH[4], bL[4];
            if (TRANSB) {
                uint32_t nrow = wn + np * 16 + (lane & 7) + (lane >> 4) * 8;
                uint32_t off = (nrow * ASTR + ks * 16 + ((lane >> 3) & 1) * 8) * 2;
                ldsm_x4(bH, bHi + off);
                ldsm_x4(bL, bLo + off);
            } else {
                uint32_t krow = ks * 16 + (lane & 15);
                uint32_t ncol = wn + np * 16 + (lane >> 4) * 8;
                uint32_t off = (krow * BSTR + ncol) * 2;
                ldsm_x4_t(bH, bHi + off);
                ldsm_x4_t(bL, bLo + off);
            }
            #pragma unroll
            for (int h = 0; h < 2; ++h) {
                #pragma unroll
                for (int mt = 0; mt < 2; ++mt) {
                    float* c = acc[mt][np * 2 + h];
                    mma_bf16(c, aH[mt], bH + h * 2);
                    mma_bf16(c, aH[mt], bL + h * 2);
                    mma_bf16(c, aL[mt], bH + h * 2);
                }
            }
        }
    }
}

// Split-epilogue helper
__device__ __forceinline__ void epi_split(bf16* Chi, bf16* Clo, long idx,
                                          float c0, float c1) {
    bf16 h0 = __float2bfloat16(c0), h1 = __float2bfloat16(c1);
    bf162 hv = __halves2bfloat162(h0, h1);
    bf162 lv = __halves2bfloat162(__float2bfloat16(c0 - __bfloat162float(h0)),
                                  __float2bfloat16(c1 - __bfloat162float(h1)));
    *(bf162*)(Chi + idx) = hv;
    *(bf162*)(Clo + idx) = lv;
}

// ---------------------------------------------------------------------------
// Merged QKV projection: grid (24, 64). bx>>3 selects W/{Q,K,V} output.
//   C = (Xhi+Xlo) @ (Whi+Wlo), NN, K=HID. Outputs split hi/lo bf16.
// ---------------------------------------------------------------------------
__global__ __launch_bounds__(256)
void gemm_qkv(const bf16* __restrict__ Xhi, const bf16* __restrict__ Xlo,
              const bf16* __restrict__ W0h, const bf16* __restrict__ W0l,
              const bf16* __restrict__ W1h, const bf16* __restrict__ W1l,
              const bf16* __restrict__ W2h, const bf16* __restrict__ W2l,
              bf16* __restrict__ C0h, bf16* __restrict__ C0l,
              bf16* __restrict__ C1h, bf16* __restrict__ C1l,
              bf16* __restrict__ C2h, bf16* __restrict__ C2l)
{
    constexpr int ASZ = 128 * ASTR;
    constexpr int BSZ = 32 * BSTR;
    constexpr int STG = 2 * ASZ + 2 * BSZ;
    extern __shared__ bf16 smem[];

    const int wsel = blockIdx.x >> 3;
    const int n0 = (blockIdx.x & 7) * 128;
    const int m0 = blockIdx.y * 128;

    const bf16* Bhi = (wsel == 0) ? W0h : (wsel == 1) ? W1h : W2h;
    const bf16* Blo = (wsel == 0) ? W0l : (wsel == 1) ? W1l : W2l;
    bf16* Chi = (wsel == 0) ? C0h : (wsel == 1) ? C1h : C2h;
    bf16* Clo = (wsel == 0) ? C0l : (wsel == 1) ? C1l : C2l;

    const int tid  = threadIdx.x;
    const int lane = tid & 31;
    const int wm   = ((tid >> 5) & 3) * 32;
    const int wn   = (tid >> 7) * 64;

    uint32_t aHiS[NSTG], aLoS[NSTG], bHiS[NSTG], bLoS[NSTG];
    #pragma unroll
    for (int s = 0; s < NSTG; ++s) {
        uint32_t base = smem_u32(smem + s * STG);
        aHiS[s] = base;
        aLoS[s] = base + ASZ * 2;
        bHiS[s] = base + 2 * ASZ * 2;
        bLoS[s] = base + (2 * ASZ + BSZ) * 2;
    }

    auto issue = [&](int kt, int s) {
        if (kt < HID) {
            #pragma unroll
            for (int i = 0; i < 2; ++i) {
                int q = tid + i * 256;
                int r = q >> 2, c = (q & 3) * 8;
                uint32_t doff = (uint32_t)(r * ASTR + c) * 2;
                cpa16(aHiS[s] + doff, Xhi + (long)(m0 + r) * HID + kt + c);
                cpa16(aLoS[s] + doff, Xlo + (long)(m0 + r) * HID + kt + c);
                int kk = q >> 4, nn = (q & 15) * 8;
                uint32_t boff = (uint32_t)(kk * BSTR + nn) * 2;
                cpa16(bHiS[s] + boff, Bhi + (long)(kt + kk) * DIM + n0 + nn);
                cpa16(bLoS[s] + boff, Blo + (long)(kt + kk) * DIM + n0 + nn);
            }
        }
        CP_COMMIT();
    };

    float acc[2][8][4];
    #pragma unroll
    for (int i = 0; i < 2; ++i)
        #pragma unroll
        for (int j = 0; j < 8; ++j)
            #pragma unroll
            for (int t = 0; t < 4; ++t) acc[i][j][t] = 0.f;

    issue(0, 0);
    issue(32, 1);

    int s = 0;
    for (int kt = 0; kt < HID; kt += 32) {
        CP_WAIT1();
        __syncthreads();
        issue(kt + 64, (s + 2) % NSTG);
        mma_tile<false>(acc, aHiS[s], aLoS[s], bHiS[s], bLoS[s], wm, wn, lane);
        s = (s + 1) % NSTG;
        __syncthreads();
    }

    #pragma unroll
    for (int mt = 0; mt < 2; ++mt) {
        #pragma unroll
        for (int nt = 0; nt < 8; ++nt) {
            int row = m0 + wm + mt * 16 + (lane >> 2);
            int col = n0 + wn + nt * 8 + (lane & 3) * 2;
            epi_split(Chi, Clo, (long)row * DIM + col,
                      acc[mt][nt][0], acc[mt][nt][1]);
            epi_split(Chi, Clo, (long)(row + 8) * DIM + col,
                      acc[mt][nt][2], acc[mt][nt][3]);
        }
    }
}

// ---------------------------------------------------------------------------
// Scores GEMM (NT, causal): P = SCALE * (Qh+Ql) @ (Kh+Kl)^T, fp32 out.
// Block-level skip above diagonal; warp-level skip on diagonal blocks.
// ---------------------------------------------------------------------------
__global__ __launch_bounds__(256)
void gemm_scores(const bf16* __restrict__ Ahi, const bf16* __restrict__ Alo,
                 const bf16* __restrict__ Bhi, const bf16* __restrict__ Blo,
                 float* __restrict__ Cf)
{
    constexpr int ASZ = 128 * ASTR;
    constexpr int STG = 4 * ASZ;
    extern __shared__ bf16 smem[];

    const int m0 = blockIdx.y * 128;
    const int n0 = blockIdx.x * 128;
    if (n0 > m0 + 127) return;

    const long zoff = (long)blockIdx.z * SEQ * DIM;
    Ahi += zoff; Alo += zoff; Bhi += zoff; Blo += zoff;
    Cf += (long)blockIdx.z * SEQ * SEQ;

    const int tid  = threadIdx.x;
    const int lane = tid & 31;
    const int wm   = ((tid >> 5) & 3) * 32;
    const int wn   = (tid >> 7) * 64;
    // warp strip rows [m0+wm, m0+wm+31], cols [n0+wn, n0+wn+63]
    const bool active = (n0 + wn) <= (m0 + wm + 31);

    uint32_t aHiS[NSTG], aLoS[NSTG], bHiS[NSTG], bLoS[NSTG];
    #pragma unroll
    for (int s = 0; s < NSTG; ++s) {
        uint32_t base = smem_u32(smem + s * STG);
        aHiS[s] = base;
        aLoS[s] = base + ASZ * 2;
        bHiS[s] = base + 2 * ASZ * 2;
        bLoS[s] = base + 3 * ASZ * 2;
    }

    auto issue = [&](int kt, int s) {
        if (kt < DIM) {
            #pragma unroll
            for (int i = 0; i < 2; ++i) {
                int q = tid + i * 256;
                int r = q >> 2, c = (q & 3) * 8;
                uint32_t doff = (uint32_t)(r * ASTR + c) * 2;
                cpa16(aHiS[s] + doff, Ahi + (long)(m0 + r) * DIM + kt + c);
                cpa16(aLoS[s] + doff, Alo + (long)(m0 + r) * DIM + kt + c);
                cpa16(bHiS[s] + doff, Bhi + (long)(n0 + r) * DIM + kt + c);
                cpa16(bLoS[s] + doff, Blo + (long)(n0 + r) * DIM + kt + c);
            }
        }
        CP_COMMIT();
    };

    float acc[2][8][4];
    #pragma unroll
    for (int i = 0; i < 2; ++i)
        #pragma unroll
        for (int j = 0; j < 8; ++j)
            #pragma unroll
            for (int t = 0; t < 4; ++t) acc[i][j][t] = 0.f;

    issue(0, 0);
    issue(32, 1);

    int s = 0;
    for (int kt = 0; kt < DIM; kt += 32) {
        CP_WAIT1();
        __syncthreads();
        issue(kt + 64, (s + 2) % NSTG);
        if (active)
            mma_tile<true>(acc, aHiS[s], aLoS[s], bHiS[s], bLoS[s], wm, wn, lane);
        s = (s + 1) % NSTG;
        __syncthreads();
    }

    if (active) {
        #pragma unroll
        for (int mt = 0; mt < 2; ++mt) {
            #pragma unroll
            for (int nt = 0; nt < 8; ++nt) {
                int row = m0 + wm + mt * 16 + (lane >> 2);
                int col = n0 + wn + nt * 8 + (lane & 3) * 2;
                *(float2*)(Cf + (long)row * SEQ + col) =
                    make_float2(SCALE * acc[mt][nt][0], SCALE * acc[mt][nt][1]);
                *(float2*)(Cf + (long)(row + 8) * SEQ + col) =
                    make_float2(SCALE * acc[mt][nt][2], SCALE * acc[mt][nt][3]);
            }
        }
    }
}

// ---------------------------------------------------------------------------
// PV GEMM (NN, K bounded by causality): out = (Ph+Pl) @ (Vh+Vl), fp32 out.
// ---------------------------------------------------------------------------
__global__ __launch_bounds__(256)
void gemm_pv(const bf16* __restrict__ Ahi, const bf16* __restrict__ Alo,
             const bf16* __restrict__ Bhi, const bf16* __restrict__ Blo,
             float* __restrict__ Cf)
{
    constexpr int ASZ = 128 * ASTR;
    constexpr int BSZ = 32 * BSTR;
    constexpr int STG = 2 * ASZ + 2 * BSZ;
    extern __shared__ bf16 smem[];

    const int m0 = blockIdx.y * 128;
    const int n0 = blockIdx.x * 128;

    Ahi += (long)blockIdx.z * SEQ * SEQ;
    Alo += (long)blockIdx.z * SEQ * SEQ;
    Bhi += (long)blockIdx.z * SEQ * DIM;
    Blo += (long)blockIdx.z * SEQ * DIM;
    Cf  += (long)blockIdx.z * SEQ * DIM;

    const int tid  = threadIdx.x;
    const int lane = tid & 31;
    const int wm   = ((tid >> 5) & 3) * 32;
    const int wn   = (tid >> 7) * 64;

    const int kEnd = m0 + 128;   // P is zero beyond the diagonal

    uint32_t aHiS[NSTG], aLoS[NSTG], bHiS[NSTG], bLoS[NSTG];
    #pragma unroll
    for (int s = 0; s < NSTG; ++s) {
        uint32_t base = smem_u32(smem + s * STG);
        aHiS[s] = base;
        aLoS[s] = base + ASZ * 2;
        bHiS[s] = base + 2 * ASZ * 2;
        bLoS[s] = base + (2 * ASZ + BSZ) * 2;
    }

    auto issue = [&](int kt, int s) {
        if (kt < kEnd) {
            #pragma unroll
            for (int i = 0; i < 2; ++i) {
                int q = tid + i * 256;
                int r = q >> 2, c = (q & 3) * 8;
                uint32_t doff = (uint32_t)(r * ASTR + c) * 2;
                cpa16(aHiS[s] + doff, Ahi + (long)(m0 + r) * SEQ + kt + c);
                cpa16(aLoS[s] + doff, Alo + (long)(m0 + r) * SEQ + kt + c);
                int kk = q >> 4, nn = (q & 15) * 8;
                uint32_t boff = (uint32_t)(kk * BSTR + nn) * 2;
                cpa16(bHiS[s] + boff, Bhi + (long)(kt + kk) * DIM + n0 + nn);
                cpa16(bLoS[s] + boff, Blo + (long)(kt + kk) * DIM + n0 + nn);
            }
        }
        CP_COMMIT();
    };

    float acc[2][8][4];
    #pragma unroll
    for (int i = 0; i < 2; ++i)
        #pragma unroll
        for (int j = 0; j < 8; ++j)
            #pragma unroll
            for (int t = 0; t < 4; ++t) acc[i][j][t] = 0.f;

    issue(0, 0);
    issue(32, 1);

    int s = 0;
    for (int kt = 0; kt < kEnd; kt += 32) {
        CP_WAIT1();
        __syncthreads();
        issue(kt + 64, (s + 2) % NSTG);
        mma_tile<false>(acc, aHiS[s], aLoS[s], bHiS[s], bLoS[s], wm, wn, lane);
        s = (s + 1) % NSTG;
        __syncthreads();
    }

    #pragma unroll
    for (int mt = 0; mt < 2; ++mt) {
        #pragma unroll
        for (int nt = 0; nt < 8; ++nt) {
            int row = m0 + wm + mt * 16 + (lane >> 2);
            int col = n0 + wn + nt * 8 + (lane & 3) * 2;
            *(float2*)(Cf + (long)row * DIM + col) =
                make_float2(acc[mt][nt][0], acc[mt][nt][1]);
            *(float2*)(Cf + (long)(row + 8) * DIM + col) =
                make_float2(acc[mt][nt][2], acc[mt][nt][3]);
        }
    }
}

// ---------------------------------------------------------------------------
// Causal softmax: fp32 scores -> hi/lo bf16 probabilities (zeros past diag).
// ---------------------------------------------------------------------------
__global__ __launch_bounds__(256)
void softmax_causal(const float* __restrict__ P, bf16* __restrict__ Ph,
                    bf16* __restrict__ Pl)
{
    const int S = SEQ;
    const int i = blockIdx.x;
    const int b = blockIdx.y;
    const float* row = P + ((long)b * S + (long)i) * S;
    bf16* hrow = Ph + ((long)b * S + (long)i) * S;
    bf16* lrow = Pl + ((long)b * S + (long)i) * S;

    __shared__ float buf[SEQ];
    __shared__ float red[256];
    const int tid = threadIdx.x;
    const int L = i + 1;

    float m = -3.0e38f;
    for (int j = tid; j < L; j += 256) {
        float v = row[j];
        buf[j] = v;
        m = fmaxf(m, v);
    }
    red[tid] = m;
    __syncthreads();
    #pragma unroll
    for (int sd = 128; sd > 0; sd >>= 1) {
        if (tid < sd) red[tid] = fmaxf(red[tid], red[tid + sd]);
        __syncthreads();
    }
    m = red[0];
    __syncthreads();

    float sum = 0.f;
    for (int j = tid; j < L; j += 256) {
        float e = expf(buf[j] - m);
        buf[j] = e;
        sum += e;
    }
    red[tid] = sum;
    __syncthreads();
    #pragma unroll
    for (int sd = 128; sd > 0; sd >>= 1) {
        if (tid < sd) red[tid] += red[tid + sd];
        __syncthreads();
    }
    const float inv = 1.0f / red[0];

    for (int j = tid; j < S; j += 256) {
        float v = (j < L) ? buf[j] * inv : 0.f;
        bf16 h = __float2bfloat16(v);
        hrow[j] = h;
        lrow[j] = __float2bfloat16(v - __bfloat162float(h));
    }
}

// ---------------------------------------------------------------------------
extern "C" void kernel_launch(void* const* d_in, const int* in_sizes, int n_in,
                              void* d_out, int out_size)
{
    (void)in_sizes; (void)n_in; (void)out_size;
    const float* X  = (const float*)d_in[0];
    const float* Wq = (const float*)d_in[1];
    const float* Wk = (const float*)d_in[2];
    const float* Wv = (const float*)d_in[3];
    float* out = (float*)d_out;

    #define SYM(v, s) void* v; cudaGetSymbolAddress(&v, s)
    SYM(pP, g_P);
    SYM(pXh, g_Xhi); SYM(pXl, g_Xlo);
    SYM(pWqh, g_Wqh); SYM(pWql, g_Wql);
    SYM(pWkh, g_Wkh); SYM(pWkl, g_Wkl);
    SYM(pWvh, g_Wvh); SYM(pWvl, g_Wvl);
    SYM(pQh, g_Qh); SYM(pQl, g_Ql);
    SYM(pKh, g_Kh); SYM(pKl, g_Kl);
    SYM(pVh, g_Vh); SYM(pVl, g_Vl);
    SYM(pPh, g_Ph); SYM(pPl, g_Pl);
    #undef SYM

    const int NT_SMEM = NSTG * (4 * 128 * ASTR) * 2;                   // 122880 B
    const int NN_SMEM = NSTG * (2 * 128 * ASTR + 2 * 32 * BSTR) * 2;   // 113664 B

    cudaFuncSetAttribute(gemm_qkv,
                         cudaFuncAttributeMaxDynamicSharedMemorySize, NN_SMEM);
    cudaFuncSetAttribute(gemm_scores,
                         cudaFuncAttributeMaxDynamicSharedMemorySize, NT_SMEM);
    cudaFuncSetAttribute(gemm_pv,
                         cudaFuncAttributeMaxDynamicSharedMemorySize, NN_SMEM);

    // 0) split X and weights to bf16 hi/lo
    {
        long nX = (long)BATCH * SEQ * HID / 4;
        split_fp32<<<2048, 256>>>(X, (bf16*)pXh, (bf16*)pXl, nX);
        long nW = (long)HID * DIM / 4;
        split_fp32<<<512, 256>>>(Wq, (bf16*)pWqh, (bf16*)pWql, nW);
        split_fp32<<<512, 256>>>(Wk, (bf16*)pWkh, (bf16*)pWkl, nW);
        split_fp32<<<512, 256>>>(Wv, (bf16*)pWvh, (bf16*)pWvl, nW);
    }

    // 1) merged QKV projections
    {
        dim3 grid(24, (BATCH * SEQ) / 128, 1);
        gemm_qkv<<<grid, 256, NN_SMEM>>>(
            (bf16*)pXh, (bf16*)pXl,
            (bf16*)pWqh, (bf16*)pWql, (bf16*)pWkh, (bf16*)pWkl,
            (bf16*)pWvh, (bf16*)pWvl,
            (bf16*)pQh, (bf16*)pQl, (bf16*)pKh, (bf16*)pKl,
            (bf16*)pVh, (bf16*)pVl);
    }

    // 2) scores = (Q @ K^T) * SCALE, lower-tri blocks only
    {
        dim3 grid(SEQ / 128, SEQ / 128, BATCH);
        gemm_scores<<<grid, 256, NT_SMEM>>>(
            (bf16*)pQh, (bf16*)pQl, (bf16*)pKh, (bf16*)pKl, (float*)pP);
    }

    // 3) causal softmax -> hi/lo bf16 probabilities
    {
        dim3 grid(SEQ, BATCH);
        softmax_causal<<<grid, 256>>>((float*)pP, (bf16*)pPh, (bf16*)pPl);
    }

    // 4) out = P @ V, K bounded per M-tile by causality
    {
        dim3 grid(DIM / 128, SEQ / 128, BATCH);
        gemm_pv<<<grid, 256, NN_SMEM>>>(
            (bf16*)pPh, (bf16*)pPl, (bf16*)pVh, (bf16*)pVl, out);
    }
}

// round 8
// speedup vs baseline: 1.0212x; 1.0001x over previous
#include <cuda_runtime.h>
#include <cuda_bf16.h>
#include <cstdint>
#include <math.h>

// Problem shapes (fixed by the dataset)
#define BATCH 4
#define SEQ   2048
#define HID   1024
#define DIM   1024
#define SCALE 0.03125f   // 1/sqrt(1024)

typedef __nv_bfloat16 bf16;
typedef __nv_bfloat162 bf162;

// Scratch (device globals; runtime allocation is forbidden)
__device__ float g_P[(long)BATCH * SEQ * SEQ];
__device__ bf16 g_Xhi[(long)BATCH * SEQ * HID];
__device__ bf16 g_Xlo[(long)BATCH * SEQ * HID];
__device__ bf16 g_Wqh[(long)HID * DIM];
__device__ bf16 g_Wql[(long)HID * DIM];
__device__ bf16 g_Wkh[(long)HID * DIM];
__device__ bf16 g_Wkl[(long)HID * DIM];
__device__ bf16 g_Wvh[(long)HID * DIM];
__device__ bf16 g_Wvl[(long)HID * DIM];
__device__ bf16 g_Qh[(long)BATCH * SEQ * DIM];
__device__ bf16 g_Ql[(long)BATCH * SEQ * DIM];
__device__ bf16 g_Kh[(long)BATCH * SEQ * DIM];
__device__ bf16 g_Kl[(long)BATCH * SEQ * DIM];
__device__ bf16 g_Vh[(long)BATCH * SEQ * DIM];
__device__ bf16 g_Vl[(long)BATCH * SEQ * DIM];
__device__ bf16 g_Ph[(long)BATCH * SEQ * SEQ];
__device__ bf16 g_Pl[(long)BATCH * SEQ * SEQ];

// ---------------------------------------------------------------------------
// PTX helpers (baseline sm_80-level PTX — safe for plain sm_103 target)
// ---------------------------------------------------------------------------
__device__ __forceinline__ uint32_t smem_u32(const void* p) {
    uint32_t a;
    asm("{ .reg .u64 t; cvta.to.shared.u64 t, %1; cvt.u32.u64 %0, t; }"
        : "=r"(a) : "l"(p));
    return a;
}

__device__ __forceinline__ void cpa16(uint32_t dst, const void* src) {
    asm volatile("cp.async.cg.shared.global [%0], [%1], 16;"
                 :: "r"(dst), "l"(src));
}
#define CP_COMMIT() asm volatile("cp.async.commit_group;" ::: "memory")
#define CP_WAIT1()  asm volatile("cp.async.wait_group 1;" ::: "memory")

__device__ __forceinline__ void ldsm_x4(uint32_t* r, uint32_t addr) {
    asm volatile("ldmatrix.sync.aligned.m8n8.x4.shared.b16 {%0,%1,%2,%3}, [%4];"
                 : "=r"(r[0]), "=r"(r[1]), "=r"(r[2]), "=r"(r[3]) : "r"(addr));
}
__device__ __forceinline__ void ldsm_x4_t(uint32_t* r, uint32_t addr) {
    asm volatile("ldmatrix.sync.aligned.m8n8.x4.trans.shared.b16 {%0,%1,%2,%3}, [%4];"
                 : "=r"(r[0]), "=r"(r[1]), "=r"(r[2]), "=r"(r[3]) : "r"(addr));
}

__device__ __forceinline__ void mma_bf16(float* c, const uint32_t* a,
                                         const uint32_t* b) {
    asm volatile(
        "mma.sync.aligned.m16n8k16.row.col.f32.bf16.bf16.f32 "
        "{%0,%1,%2,%3}, {%4,%5,%6,%7}, {%8,%9}, {%0,%1,%2,%3};"
        : "+f"(c[0]), "+f"(c[1]), "+f"(c[2]), "+f"(c[3])
        : "r"(a[0]), "r"(a[1]), "r"(a[2]), "r"(a[3]), "r"(b[0]), "r"(b[1]));
}

// ---------------------------------------------------------------------------
// fp32 -> (hi, lo) bf16 split, elementwise (n multiple of 4)
// ---------------------------------------------------------------------------
__global__ __launch_bounds__(256)
void split_fp32(const float* __restrict__ src, bf16* __restrict__ hi,
                bf16* __restrict__ lo, long n4)
{
    long i = blockIdx.x * 256 + threadIdx.x;
    long stride = (long)gridDim.x * 256;
    for (; i < n4; i += stride) {
        float4 v = *(const float4*)(src + i * 4);
        bf16 hx = __float2bfloat16(v.x), hy = __float2bfloat16(v.y);
        bf16 hz = __float2bfloat16(v.z), hw = __float2bfloat16(v.w);
        bf162 h0 = __halves2bfloat162(hx, hy);
        bf162 h1 = __halves2bfloat162(hz, hw);
        bf162 l0 = __halves2bfloat162(__float2bfloat16(v.x - __bfloat162float(hx)),
                                      __float2bfloat16(v.y - __bfloat162float(hy)));
        bf162 l1 = __halves2bfloat162(__float2bfloat16(v.z - __bfloat162float(hz)),
                                      __float2bfloat16(v.w - __bfloat162float(hw)));
        uint2 hu, lu;
        hu.x = reinterpret_cast<uint32_t&>(h0); hu.y = reinterpret_cast<uint32_t&>(h1);
        lu.x = reinterpret_cast<uint32_t&>(l0); lu.y = reinterpret_cast<uint32_t&>(l1);
        *(uint2*)(hi + i * 4) = hu;
        *(uint2*)(lo + i * 4) = lu;
    }
}

// ---------------------------------------------------------------------------
// Shared GEMM config: BM=BN=128, BK=32, 256 threads, 8 warps (4m x 2n),
// warp tile 32x64. 3-stage cp.async pipeline. 3-term Markidis bf16 split.
// ---------------------------------------------------------------------------
#define ASTR 40    // bf16 row stride A / B(NT): 80B, ldmatrix conflict-free
#define BSTR 136   // bf16 row stride B(NN) [k][n]: 272B, conflict-free
#define NSTG 3

// Inner MMA over one staged k-tile (proven R4 loop). A in [m][k] stride ASTR;
// B in [n][k] stride ASTR (NT) or [k][n] stride BSTR (NN).
template <bool TRANSB>
__device__ __forceinline__ void mma_tile(
    float acc[2][8][4], uint32_t aHi, uint32_t aLo, uint32_t bHi, uint32_t bLo,
    int wm, int wn, int lane)
{
    #pragma unroll
    for (int ks = 0; ks < 2; ++ks) {
        uint32_t aH[2][4], aL[2][4];
        #pragma unroll
        for (int mt = 0; mt < 2; ++mt) {
            uint32_t off =
                ((uint32_t)(wm + mt * 16 + (lane & 15)) * ASTR +
                 ks * 16 + (lane >> 4) * 8) * 2;
            ldsm_x4(aH[mt], aHi + off);
            ldsm_x4(aL[mt], aLo + off);
        }
        #pragma unroll
        for (int np = 0; np < 4; ++np) {
            uint32_t bH[4], bL[4];
            if (TRANSB) {
                uint32_t nrow = wn + np * 16 + (lane & 7) + (lane >> 4) * 8;
                uint32_t off = (nrow * ASTR + ks * 16 + ((lane >> 3) & 1) * 8) * 2;
                ldsm_x4(bH, bHi + off);
                ldsm_x4(bL, bLo + off);
            } else {
                uint32_t krow = ks * 16 + (lane & 15);
                uint32_t ncol = wn + np * 16 + (lane >> 4) * 8;
                uint32_t off = (krow * BSTR + ncol) * 2;
                ldsm_x4_t(bH, bHi + off);
                ldsm_x4_t(bL, bLo + off);
            }
            #pragma unroll
            for (int h = 0; h < 2; ++h) {
                #pragma unroll
                for (int mt = 0; mt < 2; ++mt) {
                    float* c = acc[mt][np * 2 + h];
                    mma_bf16(c, aH[mt], bH + h * 2);
                    mma_bf16(c, aH[mt], bL + h * 2);
                    mma_bf16(c, aL[mt], bH + h * 2);
                }
            }
        }
    }
}

// Split-epilogue helper
__device__ __forceinline__ void epi_split(bf16* Chi, bf16* Clo, long idx,
                                          float c0, float c1) {
    bf16 h0 = __float2bfloat16(c0), h1 = __float2bfloat16(c1);
    bf162 hv = __halves2bfloat162(h0, h1);
    bf162 lv = __halves2bfloat162(__float2bfloat16(c0 - __bfloat162float(h0)),
                                  __float2bfloat16(c1 - __bfloat162float(h1)));
    *(bf162*)(Chi + idx) = hv;
    *(bf162*)(Clo + idx) = lv;
}

// ---------------------------------------------------------------------------
// Merged QKV projection: grid (24, 64). bx>>3 selects W/{Q,K,V} output.
//   C = (Xhi+Xlo) @ (Whi+Wlo), NN, K=HID. Outputs split hi/lo bf16.
// ---------------------------------------------------------------------------
__global__ __launch_bounds__(256)
void gemm_qkv(const bf16* __restrict__ Xhi, const bf16* __restrict__ Xlo,
              const bf16* __restrict__ W0h, const bf16* __restrict__ W0l,
              const bf16* __restrict__ W1h, const bf16* __restrict__ W1l,
              const bf16* __restrict__ W2h, const bf16* __restrict__ W2l,
              bf16* __restrict__ C0h, bf16* __restrict__ C0l,
              bf16* __restrict__ C1h, bf16* __restrict__ C1l,
              bf16* __restrict__ C2h, bf16* __restrict__ C2l)
{
    constexpr int ASZ = 128 * ASTR;
    constexpr int BSZ = 32 * BSTR;
    constexpr int STG = 2 * ASZ + 2 * BSZ;
    extern __shared__ bf16 smem[];

    const int wsel = blockIdx.x >> 3;
    const int n0 = (blockIdx.x & 7) * 128;
    const int m0 = blockIdx.y * 128;

    const bf16* Bhi = (wsel == 0) ? W0h : (wsel == 1) ? W1h : W2h;
    const bf16* Blo = (wsel == 0) ? W0l : (wsel == 1) ? W1l : W2l;
    bf16* Chi = (wsel == 0) ? C0h : (wsel == 1) ? C1h : C2h;
    bf16* Clo = (wsel == 0) ? C0l : (wsel == 1) ? C1l : C2l;

    const int tid  = threadIdx.x;
    const int lane = tid & 31;
    const int wm   = ((tid >> 5) & 3) * 32;
    const int wn   = (tid >> 7) * 64;

    uint32_t aHiS[NSTG], aLoS[NSTG], bHiS[NSTG], bLoS[NSTG];
    #pragma unroll
    for (int s = 0; s < NSTG; ++s) {
        uint32_t base = smem_u32(smem + s * STG);
        aHiS[s] = base;
        aLoS[s] = base + ASZ * 2;
        bHiS[s] = base + 2 * ASZ * 2;
        bLoS[s] = base + (2 * ASZ + BSZ) * 2;
    }

    auto issue = [&](int kt, int s) {
        if (kt < HID) {
            #pragma unroll
            for (int i = 0; i < 2; ++i) {
                int q = tid + i * 256;
                int r = q >> 2, c = (q & 3) * 8;
                uint32_t doff = (uint32_t)(r * ASTR + c) * 2;
                cpa16(aHiS[s] + doff, Xhi + (long)(m0 + r) * HID + kt + c);
                cpa16(aLoS[s] + doff, Xlo + (long)(m0 + r) * HID + kt + c);
                int kk = q >> 4, nn = (q & 15) * 8;
                uint32_t boff = (uint32_t)(kk * BSTR + nn) * 2;
                cpa16(bHiS[s] + boff, Bhi + (long)(kt + kk) * DIM + n0 + nn);
                cpa16(bLoS[s] + boff, Blo + (long)(kt + kk) * DIM + n0 + nn);
            }
        }
        CP_COMMIT();
    };

    float acc[2][8][4];
    #pragma unroll
    for (int i = 0; i < 2; ++i)
        #pragma unroll
        for (int j = 0; j < 8; ++j)
            #pragma unroll
            for (int t = 0; t < 4; ++t) acc[i][j][t] = 0.f;

    issue(0, 0);
    issue(32, 1);

    int s = 0;
    for (int kt = 0; kt < HID; kt += 32) {
        CP_WAIT1();
        __syncthreads();
        issue(kt + 64, (s + 2) % NSTG);
        mma_tile<false>(acc, aHiS[s], aLoS[s], bHiS[s], bLoS[s], wm, wn, lane);
        s = (s + 1) % NSTG;
        __syncthreads();
    }

    #pragma unroll
    for (int mt = 0; mt < 2; ++mt) {
        #pragma unroll
        for (int nt = 0; nt < 8; ++nt) {
            int row = m0 + wm + mt * 16 + (lane >> 2);
            int col = n0 + wn + nt * 8 + (lane & 3) * 2;
            epi_split(Chi, Clo, (long)row * DIM + col,
                      acc[mt][nt][0], acc[mt][nt][1]);
            epi_split(Chi, Clo, (long)(row + 8) * DIM + col,
                      acc[mt][nt][2], acc[mt][nt][3]);
        }
    }
}

// ---------------------------------------------------------------------------
// Scores GEMM (NT, causal): P = SCALE * (Qh+Ql) @ (Kh+Kl)^T, fp32 out.
// Block-level skip above diagonal; warp-level skip on diagonal blocks.
// ---------------------------------------------------------------------------
__global__ __launch_bounds__(256)
void gemm_scores(const bf16* __restrict__ Ahi, const bf16* __restrict__ Alo,
                 const bf16* __restrict__ Bhi, const bf16* __restrict__ Blo,
                 float* __restrict__ Cf)
{
    constexpr int ASZ = 128 * ASTR;
    constexpr int STG = 4 * ASZ;
    extern __shared__ bf16 smem[];

    const int m0 = blockIdx.y * 128;
    const int n0 = blockIdx.x * 128;
    if (n0 > m0 + 127) return;

    const long zoff = (long)blockIdx.z * SEQ * DIM;
    Ahi += zoff; Alo += zoff; Bhi += zoff; Blo += zoff;
    Cf += (long)blockIdx.z * SEQ * SEQ;

    const int tid  = threadIdx.x;
    const int lane = tid & 31;
    const int wm   = ((tid >> 5) & 3) * 32;
    const int wn   = (tid >> 7) * 64;
    // warp strip rows [m0+wm, m0+wm+31], cols [n0+wn, n0+wn+63]
    const bool active = (n0 + wn) <= (m0 + wm + 31);

    uint32_t aHiS[NSTG], aLoS[NSTG], bHiS[NSTG], bLoS[NSTG];
    #pragma unroll
    for (int s = 0; s < NSTG; ++s) {
        uint32_t base = smem_u32(smem + s * STG);
        aHiS[s] = base;
        aLoS[s] = base + ASZ * 2;
        bHiS[s] = base + 2 * ASZ * 2;
        bLoS[s] = base + 3 * ASZ * 2;
    }

    auto issue = [&](int kt, int s) {
        if (kt < DIM) {
            #pragma unroll
            for (int i = 0; i < 2; ++i) {
                int q = tid + i * 256;
                int r = q >> 2, c = (q & 3) * 8;
                uint32_t doff = (uint32_t)(r * ASTR + c) * 2;
                cpa16(aHiS[s] + doff, Ahi + (long)(m0 + r) * DIM + kt + c);
                cpa16(aLoS[s] + doff, Alo + (long)(m0 + r) * DIM + kt + c);
                cpa16(bHiS[s] + doff, Bhi + (long)(n0 + r) * DIM + kt + c);
                cpa16(bLoS[s] + doff, Blo + (long)(n0 + r) * DIM + kt + c);
            }
        }
        CP_COMMIT();
    };

    float acc[2][8][4];
    #pragma unroll
    for (int i = 0; i < 2; ++i)
        #pragma unroll
        for (int j = 0; j < 8; ++j)
            #pragma unroll
            for (int t = 0; t < 4; ++t) acc[i][j][t] = 0.f;

    issue(0, 0);
    issue(32, 1);

    int s = 0;
    for (int kt = 0; kt < DIM; kt += 32) {
        CP_WAIT1();
        __syncthreads();
        issue(kt + 64, (s + 2) % NSTG);
        if (active)
            mma_tile<true>(acc, aHiS[s], aLoS[s], bHiS[s], bLoS[s], wm, wn, lane);
        s = (s + 1) % NSTG;
        __syncthreads();
    }

    if (active) {
        #pragma unroll
        for (int mt = 0; mt < 2; ++mt) {
            #pragma unroll
            for (int nt = 0; nt < 8; ++nt) {
                int row = m0 + wm + mt * 16 + (lane >> 2);
                int col = n0 + wn + nt * 8 + (lane & 3) * 2;
                *(float2*)(Cf + (long)row * SEQ + col) =
                    make_float2(SCALE * acc[mt][nt][0], SCALE * acc[mt][nt][1]);
                *(float2*)(Cf + (long)(row + 8) * SEQ + col) =
                    make_float2(SCALE * acc[mt][nt][2], SCALE * acc[mt][nt][3]);
            }
        }
    }
}

// ---------------------------------------------------------------------------
// PV GEMM (NN, K bounded by causality): out = (Ph+Pl) @ (Vh+Vl), fp32 out.
// ---------------------------------------------------------------------------
__global__ __launch_bounds__(256)
void gemm_pv(const bf16* __restrict__ Ahi, const bf16* __restrict__ Alo,
             const bf16* __restrict__ Bhi, const bf16* __restrict__ Blo,
             float* __restrict__ Cf)
{
    constexpr int ASZ = 128 * ASTR;
    constexpr int BSZ = 32 * BSTR;
    constexpr int STG = 2 * ASZ + 2 * BSZ;
    extern __shared__ bf16 smem[];

    const int m0 = blockIdx.y * 128;
    const int n0 = blockIdx.x * 128;

    Ahi += (long)blockIdx.z * SEQ * SEQ;
    Alo += (long)blockIdx.z * SEQ * SEQ;
    Bhi += (long)blockIdx.z * SEQ * DIM;
    Blo += (long)blockIdx.z * SEQ * DIM;
    Cf  += (long)blockIdx.z * SEQ * DIM;

    const int tid  = threadIdx.x;
    const int lane = tid & 31;
    const int wm   = ((tid >> 5) & 3) * 32;
    const int wn   = (tid >> 7) * 64;

    const int kEnd = m0 + 128;   // P is zero beyond the diagonal

    uint32_t aHiS[NSTG], aLoS[NSTG], bHiS[NSTG], bLoS[NSTG];
    #pragma unroll
    for (int s = 0; s < NSTG; ++s) {
        uint32_t base = smem_u32(smem + s * STG);
        aHiS[s] = base;
        aLoS[s] = base + ASZ * 2;
        bHiS[s] = base + 2 * ASZ * 2;
        bLoS[s] = base + (2 * ASZ + BSZ) * 2;
    }

    auto issue = [&](int kt, int s) {
        if (kt < kEnd) {
            #pragma unroll
            for (int i = 0; i < 2; ++i) {
                int q = tid + i * 256;
                int r = q >> 2, c = (q & 3) * 8;
                uint32_t doff = (uint32_t)(r * ASTR + c) * 2;
                cpa16(aHiS[s] + doff, Ahi + (long)(m0 + r) * SEQ + kt + c);
                cpa16(aLoS[s] + doff, Alo + (long)(m0 + r) * SEQ + kt + c);
                int kk = q >> 4, nn = (q & 15) * 8;
                uint32_t boff = (uint32_t)(kk * BSTR + nn) * 2;
                cpa16(bHiS[s] + boff, Bhi + (long)(kt + kk) * DIM + n0 + nn);
                cpa16(bLoS[s] + boff, Blo + (long)(kt + kk) * DIM + n0 + nn);
            }
        }
        CP_COMMIT();
    };

    float acc[2][8][4];
    #pragma unroll
    for (int i = 0; i < 2; ++i)
        #pragma unroll
        for (int j = 0; j < 8; ++j)
            #pragma unroll
            for (int t = 0; t < 4; ++t) acc[i][j][t] = 0.f;

    issue(0, 0);
    issue(32, 1);

    int s = 0;
    for (int kt = 0; kt < kEnd; kt += 32) {
        CP_WAIT1();
        __syncthreads();
        issue(kt + 64, (s + 2) % NSTG);
        mma_tile<false>(acc, aHiS[s], aLoS[s], bHiS[s], bLoS[s], wm, wn, lane);
        s = (s + 1) % NSTG;
        __syncthreads();
    }

    #pragma unroll
    for (int mt = 0; mt < 2; ++mt) {
        #pragma unroll
        for (int nt = 0; nt < 8; ++nt) {
            int row = m0 + wm + mt * 16 + (lane >> 2);
            int col = n0 + wn + nt * 8 + (lane & 3) * 2;
            *(float2*)(Cf + (long)row * DIM + col) =
                make_float2(acc[mt][nt][0], acc[mt][nt][1]);
            *(float2*)(Cf + (long)(row + 8) * DIM + col) =
                make_float2(acc[mt][nt][2], acc[mt][nt][3]);
        }
    }
}

// ---------------------------------------------------------------------------
// Causal softmax: fp32 scores -> hi/lo bf16 probabilities (zeros past diag).
// ---------------------------------------------------------------------------
__global__ __launch_bounds__(256)
void softmax_causal(const float* __restrict__ P, bf16* __restrict__ Ph,
                    bf16* __restrict__ Pl)
{
    const int S = SEQ;
    const int i = blockIdx.x;
    const int b = blockIdx.y;
    const float* row = P + ((long)b * S + (long)i) * S;
    bf16* hrow = Ph + ((long)b * S + (long)i) * S;
    bf16* lrow = Pl + ((long)b * S + (long)i) * S;

    __shared__ float buf[SEQ];
    __shared__ float red[256];
    const int tid = threadIdx.x;
    const int L = i + 1;

    float m = -3.0e38f;
    for (int j = tid; j < L; j += 256) {
        float v = row[j];
        buf[j] = v;
        m = fmaxf(m, v);
    }
    red[tid] = m;
    __syncthreads();
    #pragma unroll
    for (int sd = 128; sd > 0; sd >>= 1) {
        if (tid < sd) red[tid] = fmaxf(red[tid], red[tid + sd]);
        __syncthreads();
    }
    m = red[0];
    __syncthreads();

    float sum = 0.f;
    for (int j = tid; j < L; j += 256) {
        float e = expf(buf[j] - m);
        buf[j] = e;
        sum += e;
    }
    red[tid] = sum;
    __syncthreads();
    #pragma unroll
    for (int sd = 128; sd > 0; sd >>= 1) {
        if (tid < sd) red[tid] += red[tid + sd];
        __syncthreads();
    }
    const float inv = 1.0f / red[0];

    for (int j = tid; j < S; j += 256) {
        float v = (j < L) ? buf[j] * inv : 0.f;
        bf16 h = __float2bfloat16(v);
        hrow[j] = h;
        lrow[j] = __float2bfloat16(v - __bfloat162float(h));
    }
}

// ---------------------------------------------------------------------------
extern "C" void kernel_launch(void* const* d_in, const int* in_sizes, int n_in,
                              void* d_out, int out_size)
{
    (void)in_sizes; (void)n_in; (void)out_size;
    const float* X  = (const float*)d_in[0];
    const float* Wq = (const float*)d_in[1];
    const float* Wk = (const float*)d_in[2];
    const float* Wv = (const float*)d_in[3];
    float* out = (float*)d_out;

    #define SYM(v, s) void* v; cudaGetSymbolAddress(&v, s)
    SYM(pP, g_P);
    SYM(pXh, g_Xhi); SYM(pXl, g_Xlo);
    SYM(pWqh, g_Wqh); SYM(pWql, g_Wql);
    SYM(pWkh, g_Wkh); SYM(pWkl, g_Wkl);
    SYM(pWvh, g_Wvh); SYM(pWvl, g_Wvl);
    SYM(pQh, g_Qh); SYM(pQl, g_Ql);
    SYM(pKh, g_Kh); SYM(pKl, g_Kl);
    SYM(pVh, g_Vh); SYM(pVl, g_Vl);
    SYM(pPh, g_Ph); SYM(pPl, g_Pl);
    #undef SYM

    const int NT_SMEM = NSTG * (4 * 128 * ASTR) * 2;                   // 122880 B
    const int NN_SMEM = NSTG * (2 * 128 * ASTR + 2 * 32 * BSTR) * 2;   // 113664 B

    cudaFuncSetAttribute(gemm_qkv,
                         cudaFuncAttributeMaxDynamicSharedMemorySize, NN_SMEM);
    cudaFuncSetAttribute(gemm_scores,
                         cudaFuncAttributeMaxDynamicSharedMemorySize, NT_SMEM);
    cudaFuncSetAttribute(gemm_pv,
                         cudaFuncAttributeMaxDynamicSharedMemorySize, NN_SMEM);

    // 0) split X and weights to bf16 hi/lo
    {
        long nX = (long)BATCH * SEQ * HID / 4;
        split_fp32<<<2048, 256>>>(X, (bf16*)pXh, (bf16*)pXl, nX);
        long nW = (long)HID * DIM / 4;
        split_fp32<<<512, 256>>>(Wq, (bf16*)pWqh, (bf16*)pWql, nW);
        split_fp32<<<512, 256>>>(Wk, (bf16*)pWkh, (bf16*)pWkl, nW);
        split_fp32<<<512, 256>>>(Wv, (bf16*)pWvh, (bf16*)pWvl, nW);
    }

    // 1) merged QKV projections
    {
        dim3 grid(24, (BATCH * SEQ) / 128, 1);
        gemm_qkv<<<grid, 256, NN_SMEM>>>(
            (bf16*)pXh, (bf16*)pXl,
            (bf16*)pWqh, (bf16*)pWql, (bf16*)pWkh, (bf16*)pWkl,
            (bf16*)pWvh, (bf16*)pWvl,
            (bf16*)pQh, (bf16*)pQl, (bf16*)pKh, (bf16*)pKl,
            (bf16*)pVh, (bf16*)pVl);
    }

    // 2) scores = (Q @ K^T) * SCALE, lower-tri blocks only
    {
        dim3 grid(SEQ / 128, SEQ / 128, BATCH);
        gemm_scores<<<grid, 256, NT_SMEM>>>(
            (bf16*)pQh, (bf16*)pQl, (bf16*)pKh, (bf16*)pKl, (float*)pP);
    }

    // 3) causal softmax -> hi/lo bf16 probabilities
    {
        dim3 grid(SEQ, BATCH);
        softmax_causal<<<grid, 256>>>((float*)pP, (bf16*)pPh, (bf16*)pPl);
    }

    // 4) out = P @ V, K bounded per M-tile by causality
    {
        dim3 grid(DIM / 128, SEQ / 128, BATCH);
        gemm_pv<<<grid, 256, NN_SMEM>>>(
            (bf16*)pPh, (bf16*)pPl, (bf16*)pVh, (bf16*)pVl, out);
    }
}